// round 1
// baseline (speedup 1.0000x reference)
#include <cuda_runtime.h>
#include <math.h>

#define D_MODEL 1024
#define N_LAYER 4
#define D_INNER 2048
#define D_STATE 16
#define D_CONV 4
#define DT_RANK 64
#define BATCH 2
#define SEQ 1024
#define NTOK (BATCH*SEQ)          // 2048 tokens
#define DBL_W (DT_RANK + 2*D_STATE)  // 96

// ---------------- scratch (static device globals; no allocation) ----------------
__device__ float g_resid[NTOK * D_MODEL];
__device__ float g_norm [NTOK * D_MODEL];
__device__ float g_hs   [NTOK * D_MODEL];
__device__ float g_xz   [NTOK * 2 * D_INNER];
__device__ float g_xc   [NTOK * D_INNER];
__device__ float g_dbl  [NTOK * DBL_W];
__device__ float g_dt   [NTOK * D_INNER];
__device__ float g_y    [NTOK * D_INNER];

// ---------------- fused add-residual + LayerNorm ----------------
// 1 block per token; 256 threads x 4 floats = 1024 = D_MODEL
__global__ void addln_kernel(const float* __restrict__ hs_in,
                             const float* __restrict__ w,
                             const float* __restrict__ b,
                             float* __restrict__ resid,
                             float* __restrict__ out,
                             int first)
{
    int t = blockIdx.x;
    const float* hrow = hs_in + (size_t)t * D_MODEL;
    float* rrow = resid + (size_t)t * D_MODEL;
    float* orow = out + (size_t)t * D_MODEL;

    int i0 = threadIdx.x * 4;
    float4 v = *(const float4*)(hrow + i0);
    if (!first) {
        float4 r = *(const float4*)(rrow + i0);
        v.x += r.x; v.y += r.y; v.z += r.z; v.w += r.w;
    }
    *(float4*)(rrow + i0) = v;

    float s  = v.x + v.y + v.z + v.w;
    float sq = v.x*v.x + v.y*v.y + v.z*v.z + v.w*v.w;

    // warp reduce
    #pragma unroll
    for (int off = 16; off > 0; off >>= 1) {
        s  += __shfl_xor_sync(0xffffffffu, s,  off);
        sq += __shfl_xor_sync(0xffffffffu, sq, off);
    }
    __shared__ float ss[8], ssq[8];
    int wid = threadIdx.x >> 5, lid = threadIdx.x & 31;
    if (lid == 0) { ss[wid] = s; ssq[wid] = sq; }
    __syncthreads();
    __shared__ float s_mu, s_rstd;
    if (threadIdx.x == 0) {
        float ts = 0.f, tq = 0.f;
        #pragma unroll
        for (int i = 0; i < 8; i++) { ts += ss[i]; tq += ssq[i]; }
        float mu = ts * (1.0f / D_MODEL);
        float var = tq * (1.0f / D_MODEL) - mu * mu;
        s_mu = mu;
        s_rstd = rsqrtf(var + 1e-5f);
    }
    __syncthreads();
    float mu = s_mu, rstd = s_rstd;

    float4 wv = *(const float4*)(w + i0);
    float4 bv = *(const float4*)(b + i0);
    float4 o;
    o.x = (v.x - mu) * rstd * wv.x + bv.x;
    o.y = (v.y - mu) * rstd * wv.y + bv.y;
    o.z = (v.z - mu) * rstd * wv.z + bv.z;
    o.w = (v.w - mu) * rstd * wv.w + bv.w;
    *(float4*)(orow + i0) = o;
}

// ---------------- tiled SGEMM: C[M,N] = A[M,K] * W[N,K]^T ----------------
// BM=BN=64, BK=16, 256 threads, 4x4 micro-tile per thread.
// OP: 0 = plain, 1 = softplus(acc + bias[n])
template<int OP>
__global__ void gemm_kernel(const float* __restrict__ A, int lda,
                            const float* __restrict__ W, int ldw,
                            float* __restrict__ C, int ldc,
                            int N, int K,
                            const float* __restrict__ bias)
{
    __shared__ float As[16][68];
    __shared__ float Ws[16][68];

    int tid = threadIdx.x;
    int ar = tid >> 2;        // 0..63
    int ac = tid & 3;         // 0..3  -> k-offset ac*4
    int ty = tid >> 4;        // 0..15
    int tx = tid & 15;        // 0..15

    int m0 = blockIdx.y * 64;
    int n0 = blockIdx.x * 64;
    int gm = m0 + ar;
    int gn = n0 + ar;

    float acc[4][4];
    #pragma unroll
    for (int i = 0; i < 4; i++)
        #pragma unroll
        for (int j = 0; j < 4; j++) acc[i][j] = 0.f;

    for (int kt = 0; kt < K; kt += 16) {
        float4 av = *(const float4*)(A + (size_t)gm * lda + kt + ac * 4);
        float4 wv = make_float4(0.f, 0.f, 0.f, 0.f);
        if (gn < N) wv = *(const float4*)(W + (size_t)gn * ldw + kt + ac * 4);

        As[ac*4+0][ar] = av.x; As[ac*4+1][ar] = av.y;
        As[ac*4+2][ar] = av.z; As[ac*4+3][ar] = av.w;
        Ws[ac*4+0][ar] = wv.x; Ws[ac*4+1][ar] = wv.y;
        Ws[ac*4+2][ar] = wv.z; Ws[ac*4+3][ar] = wv.w;
        __syncthreads();

        #pragma unroll
        for (int k = 0; k < 16; k++) {
            float4 a = *(const float4*)(&As[k][ty*4]);
            float4 w = *(const float4*)(&Ws[k][tx*4]);
            acc[0][0] += a.x*w.x; acc[0][1] += a.x*w.y; acc[0][2] += a.x*w.z; acc[0][3] += a.x*w.w;
            acc[1][0] += a.y*w.x; acc[1][1] += a.y*w.y; acc[1][2] += a.y*w.z; acc[1][3] += a.y*w.w;
            acc[2][0] += a.z*w.x; acc[2][1] += a.z*w.y; acc[2][2] += a.z*w.z; acc[2][3] += a.z*w.w;
            acc[3][0] += a.w*w.x; acc[3][1] += a.w*w.y; acc[3][2] += a.w*w.z; acc[3][3] += a.w*w.w;
        }
        __syncthreads();
    }

    #pragma unroll
    for (int i = 0; i < 4; i++) {
        int row = m0 + ty*4 + i;
        #pragma unroll
        for (int j = 0; j < 4; j++) {
            int col = n0 + tx*4 + j;
            if (col < N) {
                float v = acc[i][j];
                if (OP == 1) {
                    v += bias[col];
                    v = (v > 20.f) ? v : log1pf(expf(v));
                }
                C[(size_t)row * ldc + col] = v;
            }
        }
    }
}

// ---------------- depthwise causal conv (D_CONV=4) + SiLU ----------------
__global__ void conv_silu_kernel(const float* __restrict__ xz,
                                 const float* __restrict__ cw,
                                 const float* __restrict__ cb,
                                 float* __restrict__ xc)
{
    int idx = blockIdx.x * blockDim.x + threadIdx.x;
    if (idx >= NTOK * D_INNER) return;
    int t = idx / D_INNER, d = idx - t * D_INNER;
    int b = t / SEQ, l = t - b * SEQ;

    float acc = cb[d];
    #pragma unroll
    for (int k = 0; k < D_CONV; k++) {
        int ls = l - (D_CONV - 1) + k;
        if (ls >= 0)
            acc += xz[((size_t)(b * SEQ + ls) * (2 * D_INNER)) + d] * cw[d * D_CONV + k];
    }
    float sig = 1.f / (1.f + __expf(-acc));
    xc[idx] = acc * sig;
}

// ---------------- selective scan: 16 lanes per (b,d) channel ----------------
__global__ void scan_kernel(const float* __restrict__ dt_arr,
                            const float* __restrict__ dbl,
                            const float* __restrict__ xc,
                            const float* __restrict__ xz,
                            const float* __restrict__ Alog,
                            const float* __restrict__ Dp,
                            float* __restrict__ y)
{
    int gid = blockIdx.x * blockDim.x + threadIdx.x;
    int ch = gid >> 4;
    int lane = gid & 15;
    if (ch >= BATCH * D_INNER) return;
    int b = ch / D_INNER, d = ch - b * D_INNER;

    float A = -__expf(Alog[d * D_STATE + lane]);
    float Dv = Dp[d];

    const float* dtp = dt_arr + (size_t)(b * SEQ) * D_INNER + d;
    const float* xp  = xc     + (size_t)(b * SEQ) * D_INNER + d;
    const float* zp  = xz     + (size_t)(b * SEQ) * (2 * D_INNER) + D_INNER + d;
    const float* bcp = dbl    + (size_t)(b * SEQ) * DBL_W;
    float*       yp  = y      + (size_t)(b * SEQ) * D_INNER + d;

    float h = 0.f;
    for (int l = 0; l < SEQ; l++) {
        float dt = dtp[(size_t)l * D_INNER];
        float x  = xp [(size_t)l * D_INNER];
        float Bs = bcp[(size_t)l * DBL_W + DT_RANK + lane];
        float Cs = bcp[(size_t)l * DBL_W + DT_RANK + D_STATE + lane];

        h = h * __expf(dt * A) + (dt * x) * Bs;

        float p = h * Cs;
        p += __shfl_xor_sync(0xffffffffu, p, 8);
        p += __shfl_xor_sync(0xffffffffu, p, 4);
        p += __shfl_xor_sync(0xffffffffu, p, 2);
        p += __shfl_xor_sync(0xffffffffu, p, 1);

        if (lane == 0) {
            float z = zp[(size_t)l * (2 * D_INNER)];
            float sig = 1.f / (1.f + __expf(-z));
            yp[(size_t)l * D_INNER] = (p + x * Dv) * (z * sig);
        }
    }
}

// ---------------- launch ----------------
extern "C" void kernel_launch(void* const* d_in, const int* in_sizes, int n_in,
                              void* d_out, int out_size)
{
    const float* hidden     = (const float*)d_in[0];
    const float* in_proj_w  = (const float*)d_in[1];
    const float* conv_w     = (const float*)d_in[2];
    const float* conv_b     = (const float*)d_in[3];
    const float* x_proj_w   = (const float*)d_in[4];
    const float* dt_proj_w  = (const float*)d_in[5];
    const float* dt_proj_b  = (const float*)d_in[6];
    const float* A_log      = (const float*)d_in[7];
    const float* Dp         = (const float*)d_in[8];
    const float* out_proj_w = (const float*)d_in[9];
    const float* norm_w     = (const float*)d_in[10];
    const float* norm_b     = (const float*)d_in[11];
    const float* normf_w    = (const float*)d_in[12];
    const float* normf_b    = (const float*)d_in[13];
    float* out = (float*)d_out;

    float *p_resid, *p_norm, *p_hs, *p_xz, *p_xc, *p_dbl, *p_dt, *p_y;
    cudaGetSymbolAddress((void**)&p_resid, g_resid);
    cudaGetSymbolAddress((void**)&p_norm,  g_norm);
    cudaGetSymbolAddress((void**)&p_hs,    g_hs);
    cudaGetSymbolAddress((void**)&p_xz,    g_xz);
    cudaGetSymbolAddress((void**)&p_xc,    g_xc);
    cudaGetSymbolAddress((void**)&p_dbl,   g_dbl);
    cudaGetSymbolAddress((void**)&p_dt,    g_dt);
    cudaGetSymbolAddress((void**)&p_y,     g_y);

    for (int layer = 0; layer < N_LAYER; layer++) {
        const float* src = (layer == 0) ? hidden : p_hs;

        // residual add + LN
        addln_kernel<<<NTOK, 256>>>(src,
                                    norm_w + layer * D_MODEL,
                                    norm_b + layer * D_MODEL,
                                    p_resid, p_norm, layer == 0 ? 1 : 0);

        // in_proj: [2048,1024] x [4096,1024]^T -> [2048,4096]
        gemm_kernel<0><<<dim3(2 * D_INNER / 64, NTOK / 64), 256>>>(
            p_norm, D_MODEL,
            in_proj_w + (size_t)layer * 2 * D_INNER * D_MODEL, D_MODEL,
            p_xz, 2 * D_INNER, 2 * D_INNER, D_MODEL, nullptr);

        // conv + silu
        conv_silu_kernel<<<(NTOK * D_INNER + 255) / 256, 256>>>(
            p_xz, conv_w + (size_t)layer * D_INNER * D_CONV,
            conv_b + (size_t)layer * D_INNER, p_xc);

        // x_proj: [2048,2048] x [96,2048]^T -> [2048,96]
        gemm_kernel<0><<<dim3((DBL_W + 63) / 64, NTOK / 64), 256>>>(
            p_xc, D_INNER,
            x_proj_w + (size_t)layer * DBL_W * D_INNER, D_INNER,
            p_dbl, DBL_W, DBL_W, D_INNER, nullptr);

        // dt_proj + softplus: [2048,64] x [2048,64]^T -> [2048,2048]
        gemm_kernel<1><<<dim3(D_INNER / 64, NTOK / 64), 256>>>(
            p_dbl, DBL_W,
            dt_proj_w + (size_t)layer * D_INNER * DT_RANK, DT_RANK,
            p_dt, D_INNER, D_INNER, DT_RANK,
            dt_proj_b + (size_t)layer * D_INNER);

        // selective scan + gating epilogue
        scan_kernel<<<(BATCH * D_INNER * 16) / 256, 256>>>(
            p_dt, p_dbl, p_xc, p_xz,
            A_log + (size_t)layer * D_INNER * D_STATE,
            Dp + (size_t)layer * D_INNER, p_y);

        // out_proj: [2048,2048] x [1024,2048]^T -> [2048,1024]
        gemm_kernel<0><<<dim3(D_MODEL / 64, NTOK / 64), 256>>>(
            p_y, D_INNER,
            out_proj_w + (size_t)layer * D_MODEL * D_INNER, D_INNER,
            p_hs, D_MODEL, D_MODEL, D_INNER, nullptr);
    }

    // final residual add + LN -> d_out
    addln_kernel<<<NTOK, 256>>>(p_hs, normf_w, normf_b, p_resid, out, 0);
}

// round 2
// speedup vs baseline: 1.3723x; 1.3723x over previous
#include <cuda_runtime.h>
#include <cuda_bf16.h>
#include <math.h>
#include <stdint.h>

#define D_MODEL 1024
#define N_LAYER 4
#define D_INNER 2048
#define D_STATE 16
#define D_CONV 4
#define DT_RANK 64
#define BATCH 2
#define SEQ 1024
#define NTOK (BATCH*SEQ)             // 2048 tokens
#define DBL_W (DT_RANK + 2*D_STATE)  // 96

// ---------------- scratch (static device globals; no allocation) ----------------
__device__ float g_resid[NTOK * D_MODEL];
__device__ float g_norm [NTOK * D_MODEL];
__device__ float g_hs   [NTOK * D_MODEL];
__device__ float g_xz   [NTOK * 2 * D_INNER];
__device__ float g_xc   [NTOK * D_INNER];
__device__ float g_dbl  [NTOK * DBL_W];
__device__ float g_dt   [NTOK * D_INNER];
__device__ float g_y    [NTOK * D_INNER];

// ---------------- fused add-residual + LayerNorm ----------------
__global__ void addln_kernel(const float* __restrict__ hs_in,
                             const float* __restrict__ w,
                             const float* __restrict__ b,
                             float* __restrict__ resid,
                             float* __restrict__ out,
                             int first)
{
    int t = blockIdx.x;
    const float* hrow = hs_in + (size_t)t * D_MODEL;
    float* rrow = resid + (size_t)t * D_MODEL;
    float* orow = out + (size_t)t * D_MODEL;

    int i0 = threadIdx.x * 4;
    float4 v = *(const float4*)(hrow + i0);
    if (!first) {
        float4 r = *(const float4*)(rrow + i0);
        v.x += r.x; v.y += r.y; v.z += r.z; v.w += r.w;
    }
    *(float4*)(rrow + i0) = v;

    float s  = v.x + v.y + v.z + v.w;
    float sq = v.x*v.x + v.y*v.y + v.z*v.z + v.w*v.w;

    #pragma unroll
    for (int off = 16; off > 0; off >>= 1) {
        s  += __shfl_xor_sync(0xffffffffu, s,  off);
        sq += __shfl_xor_sync(0xffffffffu, sq, off);
    }
    __shared__ float ss[8], ssq[8];
    int wid = threadIdx.x >> 5, lid = threadIdx.x & 31;
    if (lid == 0) { ss[wid] = s; ssq[wid] = sq; }
    __syncthreads();
    __shared__ float s_mu, s_rstd;
    if (threadIdx.x == 0) {
        float ts = 0.f, tq = 0.f;
        #pragma unroll
        for (int i = 0; i < 8; i++) { ts += ss[i]; tq += ssq[i]; }
        float mu = ts * (1.0f / D_MODEL);
        float var = tq * (1.0f / D_MODEL) - mu * mu;
        s_mu = mu;
        s_rstd = rsqrtf(var + 1e-5f);
    }
    __syncthreads();
    float mu = s_mu, rstd = s_rstd;

    float4 wv = *(const float4*)(w + i0);
    float4 bv = *(const float4*)(b + i0);
    float4 o;
    o.x = (v.x - mu) * rstd * wv.x + bv.x;
    o.y = (v.y - mu) * rstd * wv.y + bv.y;
    o.z = (v.z - mu) * rstd * wv.z + bv.z;
    o.w = (v.w - mu) * rstd * wv.w + bv.w;
    *(float4*)(orow + i0) = o;
}

// ================= tensor-core GEMM: C[M,N] = A[M,K] * W[N,K]^T =================
// bf16 split (hi+lo) x 3 MMAs for fp32-class accuracy.
// BM=128, BN=64, BK=16, 256 threads (8 warps, 4x2), warp tile 32x32.

#define BM 128
#define BN 64
#define BK 16
#define SA_STR 24                    // padded row stride in halves (48B, LDSM conflict-free)
#define A_HALVES (BM*SA_STR)         // 3072
#define B_HALVES (BN*SA_STR)         // 1536
#define STAGE_HALVES (2*A_HALVES + 2*B_HALVES)   // 9216 halves = 18KB
#define OFF_AL_B (A_HALVES*2)        // byte offsets within stage
#define OFF_BH_B (2*A_HALVES*2)
#define OFF_BL_B (2*A_HALVES*2 + B_HALVES*2)

__device__ __forceinline__ uint32_t smem_u32(const void* p) {
    return (uint32_t)__cvta_generic_to_shared(p);
}
__device__ __forceinline__ void ldsm_x4(uint32_t& r0, uint32_t& r1, uint32_t& r2, uint32_t& r3, uint32_t addr) {
    asm volatile("ldmatrix.sync.aligned.m8n8.x4.shared.b16 {%0,%1,%2,%3}, [%4];\n"
                 : "=r"(r0), "=r"(r1), "=r"(r2), "=r"(r3) : "r"(addr));
}
__device__ __forceinline__ void ldsm_x2(uint32_t& r0, uint32_t& r1, uint32_t addr) {
    asm volatile("ldmatrix.sync.aligned.m8n8.x2.shared.b16 {%0,%1}, [%2];\n"
                 : "=r"(r0), "=r"(r1) : "r"(addr));
}
__device__ __forceinline__ void mma_bf16(float* c, const uint32_t* a, const uint32_t* b) {
    asm volatile("mma.sync.aligned.m16n8k16.row.col.f32.bf16.bf16.f32 "
                 "{%0,%1,%2,%3}, {%4,%5,%6,%7}, {%8,%9}, {%0,%1,%2,%3};\n"
                 : "+f"(c[0]), "+f"(c[1]), "+f"(c[2]), "+f"(c[3])
                 : "r"(a[0]), "r"(a[1]), "r"(a[2]), "r"(a[3]), "r"(b[0]), "r"(b[1]));
}

// OP: 0 = plain, 1 = softplus(acc + bias[n])
template<int OP>
__global__ __launch_bounds__(256, 2) void mma_gemm(
    const float* __restrict__ A, int lda,
    const float* __restrict__ W, int ldw,
    float* __restrict__ C, int ldc,
    int N, int K, const float* __restrict__ bias)
{
    __shared__ __align__(16) __nv_bfloat16 smem[2][STAGE_HALVES];

    int tid = threadIdx.x;
    int lane = tid & 31, warp = tid >> 5;
    int wm = warp & 3, wn = warp >> 2;
    int m0 = blockIdx.y * BM, n0 = blockIdx.x * BN;

    // global load mapping
    int arow = tid >> 1;              // 0..127
    int akoff = (tid & 1) * 8;        // 0 or 8
    int brow = tid >> 2;              // 0..63
    int bkoff = (tid & 3) * 4;        // 0,4,8,12

    const float* Aload = A + (size_t)(m0 + arow) * lda + akoff;
    bool bvalid = (n0 + brow) < N;
    const float* Bload = W + (size_t)(n0 + brow) * ldw + bkoff;

    float acc[2][4][4];
    #pragma unroll
    for (int mi = 0; mi < 2; mi++)
        #pragma unroll
        for (int ni = 0; ni < 4; ni++)
            #pragma unroll
            for (int j = 0; j < 4; j++) acc[mi][ni][j] = 0.f;

    // ldmatrix lane offsets (bytes within stage)
    uint32_t aoff[2], boff[4];
    #pragma unroll
    for (int mi = 0; mi < 2; mi++) {
        int r = wm * 32 + mi * 16 + (lane & 15);
        int c = ((lane >> 4) << 3);
        aoff[mi] = (uint32_t)((r * SA_STR + c) * 2);
    }
    #pragma unroll
    for (int ni = 0; ni < 4; ni++) {
        int r = wn * 32 + ni * 8 + (lane & 7);
        int c = (((lane >> 3) & 1) << 3);
        boff[ni] = (uint32_t)((r * SA_STR + c) * 2);
    }
    uint32_t sbase = smem_u32(&smem[0][0]);

    int KT = K / BK;

    float4 ra0, ra1, rb0;
    ra0 = *(const float4*)(Aload);
    ra1 = *(const float4*)(Aload + 4);
    rb0 = bvalid ? *(const float4*)(Bload) : make_float4(0.f, 0.f, 0.f, 0.f);

    int cur = 0;
    for (int kt = 0; kt < KT; kt++) {
        // store current tile (fp32 -> hi/lo bf16) into smem[cur]
        __nv_bfloat16* Ah = &smem[cur][0];
        __nv_bfloat16* Al = Ah + A_HALVES;
        __nv_bfloat16* Bh = Ah + 2 * A_HALVES;
        __nv_bfloat16* Bl = Bh + B_HALVES;

        float av[8] = {ra0.x, ra0.y, ra0.z, ra0.w, ra1.x, ra1.y, ra1.z, ra1.w};
        #pragma unroll
        for (int j = 0; j < 4; j++) {
            float v0 = av[2*j], v1 = av[2*j+1];
            __nv_bfloat16 h0 = __float2bfloat16(v0);
            __nv_bfloat16 h1 = __float2bfloat16(v1);
            __nv_bfloat16 l0 = __float2bfloat16(v0 - __bfloat162float(h0));
            __nv_bfloat16 l1 = __float2bfloat16(v1 - __bfloat162float(h1));
            *(__nv_bfloat162*)&Ah[arow * SA_STR + akoff + 2*j] = __halves2bfloat162(h0, h1);
            *(__nv_bfloat162*)&Al[arow * SA_STR + akoff + 2*j] = __halves2bfloat162(l0, l1);
        }
        float bv[4] = {rb0.x, rb0.y, rb0.z, rb0.w};
        #pragma unroll
        for (int j = 0; j < 2; j++) {
            float v0 = bv[2*j], v1 = bv[2*j+1];
            __nv_bfloat16 h0 = __float2bfloat16(v0);
            __nv_bfloat16 h1 = __float2bfloat16(v1);
            __nv_bfloat16 l0 = __float2bfloat16(v0 - __bfloat162float(h0));
            __nv_bfloat16 l1 = __float2bfloat16(v1 - __bfloat162float(h1));
            *(__nv_bfloat162*)&Bh[brow * SA_STR + bkoff + 2*j] = __halves2bfloat162(h0, h1);
            *(__nv_bfloat162*)&Bl[brow * SA_STR + bkoff + 2*j] = __halves2bfloat162(l0, l1);
        }
        __syncthreads();

        // prefetch next tile into registers
        if (kt + 1 < KT) {
            const float* An = Aload + (kt + 1) * BK;
            ra0 = *(const float4*)(An);
            ra1 = *(const float4*)(An + 4);
            const float* Bn = Bload + (kt + 1) * BK;
            rb0 = bvalid ? *(const float4*)(Bn) : make_float4(0.f, 0.f, 0.f, 0.f);
        }

        // compute from smem[cur]
        uint32_t base = sbase + (uint32_t)cur * (STAGE_HALVES * 2);
        uint32_t ah[2][4], al[2][4], bh[4][2], bl[4][2];
        #pragma unroll
        for (int mi = 0; mi < 2; mi++) {
            ldsm_x4(ah[mi][0], ah[mi][1], ah[mi][2], ah[mi][3], base + aoff[mi]);
            ldsm_x4(al[mi][0], al[mi][1], al[mi][2], al[mi][3], base + OFF_AL_B + aoff[mi]);
        }
        #pragma unroll
        for (int ni = 0; ni < 4; ni++) {
            ldsm_x2(bh[ni][0], bh[ni][1], base + OFF_BH_B + boff[ni]);
            ldsm_x2(bl[ni][0], bl[ni][1], base + OFF_BL_B + boff[ni]);
        }
        #pragma unroll
        for (int mi = 0; mi < 2; mi++) {
            #pragma unroll
            for (int ni = 0; ni < 4; ni++) {
                mma_bf16(acc[mi][ni], ah[mi], bh[ni]);
                mma_bf16(acc[mi][ni], ah[mi], bl[ni]);
                mma_bf16(acc[mi][ni], al[mi], bh[ni]);
            }
        }
        cur ^= 1;
    }

    // epilogue
    int crow0 = m0 + wm * 32, ccol0 = n0 + wn * 32;
    #pragma unroll
    for (int mi = 0; mi < 2; mi++) {
        #pragma unroll
        for (int ni = 0; ni < 4; ni++) {
            int r = crow0 + mi * 16 + (lane >> 2);
            int c = ccol0 + ni * 8 + (lane & 3) * 2;
            if (c < N) {
                float v0 = acc[mi][ni][0], v1 = acc[mi][ni][1];
                float v2 = acc[mi][ni][2], v3 = acc[mi][ni][3];
                if (OP == 1) {
                    float b0 = bias[c], b1 = bias[c + 1];
                    v0 += b0; v1 += b1; v2 += b0; v3 += b1;
                    v0 = (v0 > 20.f) ? v0 : log1pf(expf(v0));
                    v1 = (v1 > 20.f) ? v1 : log1pf(expf(v1));
                    v2 = (v2 > 20.f) ? v2 : log1pf(expf(v2));
                    v3 = (v3 > 20.f) ? v3 : log1pf(expf(v3));
                }
                C[(size_t)r * ldc + c]           = v0;
                C[(size_t)r * ldc + c + 1]       = v1;
                C[(size_t)(r + 8) * ldc + c]     = v2;
                C[(size_t)(r + 8) * ldc + c + 1] = v3;
            }
        }
    }
}

// ---------------- depthwise causal conv (D_CONV=4) + SiLU ----------------
__global__ void conv_silu_kernel(const float* __restrict__ xz,
                                 const float* __restrict__ cw,
                                 const float* __restrict__ cb,
                                 float* __restrict__ xc)
{
    int idx = blockIdx.x * blockDim.x + threadIdx.x;
    if (idx >= NTOK * D_INNER) return;
    int t = idx / D_INNER, d = idx - t * D_INNER;
    int b = t / SEQ, l = t - b * SEQ;

    float acc = cb[d];
    #pragma unroll
    for (int k = 0; k < D_CONV; k++) {
        int ls = l - (D_CONV - 1) + k;
        if (ls >= 0)
            acc += xz[((size_t)(b * SEQ + ls) * (2 * D_INNER)) + d] * cw[d * D_CONV + k];
    }
    float sig = 1.f / (1.f + __expf(-acc));
    xc[idx] = acc * sig;
}

// ---------------- selective scan: 16 lanes per (b,d) channel ----------------
__global__ void scan_kernel(const float* __restrict__ dt_arr,
                            const float* __restrict__ dbl,
                            const float* __restrict__ xc,
                            const float* __restrict__ xz,
                            const float* __restrict__ Alog,
                            const float* __restrict__ Dp,
                            float* __restrict__ y)
{
    int gid = blockIdx.x * blockDim.x + threadIdx.x;
    int ch = gid >> 4;
    int lane = gid & 15;
    if (ch >= BATCH * D_INNER) return;
    int b = ch / D_INNER, d = ch - b * D_INNER;

    float A = -__expf(Alog[d * D_STATE + lane]);
    float Dv = Dp[d];

    const float* dtp = dt_arr + (size_t)(b * SEQ) * D_INNER + d;
    const float* xp  = xc     + (size_t)(b * SEQ) * D_INNER + d;
    const float* zp  = xz     + (size_t)(b * SEQ) * (2 * D_INNER) + D_INNER + d;
    const float* bcp = dbl    + (size_t)(b * SEQ) * DBL_W;
    float*       yp  = y      + (size_t)(b * SEQ) * D_INNER + d;

    float h = 0.f;
    for (int l = 0; l < SEQ; l++) {
        float dt = dtp[(size_t)l * D_INNER];
        float x  = xp [(size_t)l * D_INNER];
        float Bs = bcp[(size_t)l * DBL_W + DT_RANK + lane];
        float Cs = bcp[(size_t)l * DBL_W + DT_RANK + D_STATE + lane];

        h = h * __expf(dt * A) + (dt * x) * Bs;

        float p = h * Cs;
        p += __shfl_xor_sync(0xffffffffu, p, 8);
        p += __shfl_xor_sync(0xffffffffu, p, 4);
        p += __shfl_xor_sync(0xffffffffu, p, 2);
        p += __shfl_xor_sync(0xffffffffu, p, 1);

        if (lane == 0) {
            float z = zp[(size_t)l * (2 * D_INNER)];
            float sig = 1.f / (1.f + __expf(-z));
            yp[(size_t)l * D_INNER] = (p + x * Dv) * (z * sig);
        }
    }
}

// ---------------- launch ----------------
extern "C" void kernel_launch(void* const* d_in, const int* in_sizes, int n_in,
                              void* d_out, int out_size)
{
    const float* hidden     = (const float*)d_in[0];
    const float* in_proj_w  = (const float*)d_in[1];
    const float* conv_w     = (const float*)d_in[2];
    const float* conv_b     = (const float*)d_in[3];
    const float* x_proj_w   = (const float*)d_in[4];
    const float* dt_proj_w  = (const float*)d_in[5];
    const float* dt_proj_b  = (const float*)d_in[6];
    const float* A_log      = (const float*)d_in[7];
    const float* Dp         = (const float*)d_in[8];
    const float* out_proj_w = (const float*)d_in[9];
    const float* norm_w     = (const float*)d_in[10];
    const float* norm_b     = (const float*)d_in[11];
    const float* normf_w    = (const float*)d_in[12];
    const float* normf_b    = (const float*)d_in[13];
    float* out = (float*)d_out;

    float *p_resid, *p_norm, *p_hs, *p_xz, *p_xc, *p_dbl, *p_dt, *p_y;
    cudaGetSymbolAddress((void**)&p_resid, g_resid);
    cudaGetSymbolAddress((void**)&p_norm,  g_norm);
    cudaGetSymbolAddress((void**)&p_hs,    g_hs);
    cudaGetSymbolAddress((void**)&p_xz,    g_xz);
    cudaGetSymbolAddress((void**)&p_xc,    g_xc);
    cudaGetSymbolAddress((void**)&p_dbl,   g_dbl);
    cudaGetSymbolAddress((void**)&p_dt,    g_dt);
    cudaGetSymbolAddress((void**)&p_y,     g_y);

    for (int layer = 0; layer < N_LAYER; layer++) {
        const float* src = (layer == 0) ? hidden : p_hs;

        addln_kernel<<<NTOK, 256>>>(src,
                                    norm_w + layer * D_MODEL,
                                    norm_b + layer * D_MODEL,
                                    p_resid, p_norm, layer == 0 ? 1 : 0);

        // in_proj: [2048,1024] x [4096,1024]^T -> [2048,4096]
        mma_gemm<0><<<dim3(2 * D_INNER / BN, NTOK / BM), 256>>>(
            p_norm, D_MODEL,
            in_proj_w + (size_t)layer * 2 * D_INNER * D_MODEL, D_MODEL,
            p_xz, 2 * D_INNER, 2 * D_INNER, D_MODEL, nullptr);

        conv_silu_kernel<<<(NTOK * D_INNER + 255) / 256, 256>>>(
            p_xz, conv_w + (size_t)layer * D_INNER * D_CONV,
            conv_b + (size_t)layer * D_INNER, p_xc);

        // x_proj: [2048,2048] x [96,2048]^T -> [2048,96]
        mma_gemm<0><<<dim3((DBL_W + BN - 1) / BN, NTOK / BM), 256>>>(
            p_xc, D_INNER,
            x_proj_w + (size_t)layer * DBL_W * D_INNER, D_INNER,
            p_dbl, DBL_W, DBL_W, D_INNER, nullptr);

        // dt_proj + softplus: [2048,64] x [2048,64]^T -> [2048,2048]
        mma_gemm<1><<<dim3(D_INNER / BN, NTOK / BM), 256>>>(
            p_dbl, DBL_W,
            dt_proj_w + (size_t)layer * D_INNER * DT_RANK, DT_RANK,
            p_dt, D_INNER, D_INNER, DT_RANK,
            dt_proj_b + (size_t)layer * D_INNER);

        scan_kernel<<<(BATCH * D_INNER * 16) / 256, 256>>>(
            p_dt, p_dbl, p_xc, p_xz,
            A_log + (size_t)layer * D_INNER * D_STATE,
            Dp + (size_t)layer * D_INNER, p_y);

        // out_proj: [2048,2048] x [1024,2048]^T -> [2048,1024]
        mma_gemm<0><<<dim3(D_MODEL / BN, NTOK / BM), 256>>>(
            p_y, D_INNER,
            out_proj_w + (size_t)layer * D_MODEL * D_INNER, D_INNER,
            p_hs, D_MODEL, D_MODEL, D_INNER, nullptr);
    }

    addln_kernel<<<NTOK, 256>>>(p_hs, normf_w, normf_b, p_resid, out, 0);
}

// round 3
// speedup vs baseline: 1.4329x; 1.0442x over previous
#include <cuda_runtime.h>
#include <cuda_bf16.h>
#include <math.h>
#include <stdint.h>

#define D_MODEL 1024
#define N_LAYER 4
#define D_INNER 2048
#define D_STATE 16
#define D_CONV 4
#define DT_RANK 64
#define BATCH 2
#define SEQ 1024
#define NTOK (BATCH*SEQ)             // 2048 tokens
#define DBL_W (DT_RANK + 2*D_STATE)  // 96
#define KSPLIT 4

typedef __nv_bfloat16 bf16;
typedef __nv_bfloat162 bf162;

// ---------------- scratch (static device globals; no allocation) ----------------
__device__ float g_resid[NTOK * D_MODEL];
__device__ float g_hs   [NTOK * D_MODEL];
__device__ float g_xz   [NTOK * 2 * D_INNER];
__device__ float g_xc   [NTOK * D_INNER];
__device__ float g_dbl  [NTOK * DBL_W];
__device__ float g_dt   [NTOK * D_INNER];
__device__ float g_xpart[KSPLIT * NTOK * DBL_W];

// bf16 hi/lo activations
__device__ bf16 g_normh[NTOK * D_MODEL],  g_norml[NTOK * D_MODEL];
__device__ bf16 g_xch  [NTOK * D_INNER],  g_xcl  [NTOK * D_INNER];
__device__ bf16 g_dtAh [NTOK * DT_RANK],  g_dtAl [NTOK * DT_RANK];
__device__ bf16 g_yh   [NTOK * D_INNER],  g_yl   [NTOK * D_INNER];

// bf16 hi/lo weights (converted once per launch)
__device__ bf16 g_wih[N_LAYER*2*D_INNER*D_MODEL], g_wil[N_LAYER*2*D_INNER*D_MODEL];
__device__ bf16 g_wxh[N_LAYER*DBL_W*D_INNER],     g_wxl[N_LAYER*DBL_W*D_INNER];
__device__ bf16 g_wdh[N_LAYER*D_INNER*DT_RANK],   g_wdl[N_LAYER*D_INNER*DT_RANK];
__device__ bf16 g_woh[N_LAYER*D_MODEL*D_INNER],   g_wol[N_LAYER*D_MODEL*D_INNER];

__device__ __forceinline__ void split1(float v, bf16& h, bf16& l) {
    h = __float2bfloat16(v);
    l = __float2bfloat16(v - __bfloat162float(h));
}

// ---------------- fp32 -> bf16 hi/lo conversion (weights) ----------------
__global__ void split4_kernel(const float4* __restrict__ src,
                              bf162* __restrict__ hi, bf162* __restrict__ lo, int n4)
{
    int i = blockIdx.x * blockDim.x + threadIdx.x;
    if (i >= n4) return;
    float4 v = src[i];
    bf16 h0,h1,h2,h3,l0,l1,l2,l3;
    split1(v.x,h0,l0); split1(v.y,h1,l1); split1(v.z,h2,l2); split1(v.w,h3,l3);
    hi[2*i]   = bf162(h0,h1); hi[2*i+1] = bf162(h2,h3);
    lo[2*i]   = bf162(l0,l1); lo[2*i+1] = bf162(l2,l3);
}

// ---------------- fused add-residual + LayerNorm (emits bf16 hi/lo or fp32) ----------------
__global__ void addln_kernel(const float* __restrict__ hs_in,
                             const float* __restrict__ w,
                             const float* __restrict__ b,
                             float* __restrict__ resid,
                             float* __restrict__ out_f32,
                             bf16* __restrict__ out_hi,
                             bf16* __restrict__ out_lo,
                             int first)
{
    int t = blockIdx.x;
    const float* hrow = hs_in + (size_t)t * D_MODEL;
    float* rrow = resid + (size_t)t * D_MODEL;

    int i0 = threadIdx.x * 4;
    float4 v = *(const float4*)(hrow + i0);
    if (!first) {
        float4 r = *(const float4*)(rrow + i0);
        v.x += r.x; v.y += r.y; v.z += r.z; v.w += r.w;
    }
    *(float4*)(rrow + i0) = v;

    float s  = v.x + v.y + v.z + v.w;
    float sq = v.x*v.x + v.y*v.y + v.z*v.z + v.w*v.w;
    #pragma unroll
    for (int off = 16; off > 0; off >>= 1) {
        s  += __shfl_xor_sync(0xffffffffu, s,  off);
        sq += __shfl_xor_sync(0xffffffffu, sq, off);
    }
    __shared__ float ss[8], ssq[8];
    int wid = threadIdx.x >> 5, lid = threadIdx.x & 31;
    if (lid == 0) { ss[wid] = s; ssq[wid] = sq; }
    __syncthreads();
    __shared__ float s_mu, s_rstd;
    if (threadIdx.x == 0) {
        float ts = 0.f, tq = 0.f;
        #pragma unroll
        for (int i = 0; i < 8; i++) { ts += ss[i]; tq += ssq[i]; }
        float mu = ts * (1.0f / D_MODEL);
        float var = tq * (1.0f / D_MODEL) - mu * mu;
        s_mu = mu; s_rstd = rsqrtf(var + 1e-5f);
    }
    __syncthreads();
    float mu = s_mu, rstd = s_rstd;

    float4 wv = *(const float4*)(w + i0);
    float4 bv = *(const float4*)(b + i0);
    float o0 = (v.x - mu) * rstd * wv.x + bv.x;
    float o1 = (v.y - mu) * rstd * wv.y + bv.y;
    float o2 = (v.z - mu) * rstd * wv.z + bv.z;
    float o3 = (v.w - mu) * rstd * wv.w + bv.w;

    if (out_hi) {
        bf16 h0,h1,h2,h3,l0,l1,l2,l3;
        split1(o0,h0,l0); split1(o1,h1,l1); split1(o2,h2,l2); split1(o3,h3,l3);
        size_t p = (size_t)t * D_MODEL + i0;
        *(bf162*)(out_hi + p)     = bf162(h0,h1);
        *(bf162*)(out_hi + p + 2) = bf162(h2,h3);
        *(bf162*)(out_lo + p)     = bf162(l0,l1);
        *(bf162*)(out_lo + p + 2) = bf162(l2,l3);
    } else {
        *(float4*)(out_f32 + (size_t)t * D_MODEL + i0) = make_float4(o0,o1,o2,o3);
    }
}

// ================= bf16 tensor-core GEMM: C[M,N] = A[M,K] * W[N,K]^T =================
// Inputs pre-split hi/lo bf16. 3-pass MMA: AhBh + AhBl + AlBh.
// BM=128, BN=64, BK=32, 3-stage cp.async pipeline, 8 warps (4x2), warp tile 32x32.

#define BM 128
#define BN 64
#define RS 40                        // padded row stride (halves)
#define S_AH 0
#define S_AL (BM*RS)                 // 5120
#define S_BH (2*BM*RS)               // 10240
#define S_BL (2*BM*RS + BN*RS)       // 12800
#define STAGE_H (2*BM*RS + 2*BN*RS)  // 15360 halves
#define STAGE_B (STAGE_H*2)          // 30720 bytes
#define STAGES 3
#define GEMM_SMEM (STAGES*STAGE_B)   // 92160 bytes

__device__ __forceinline__ uint32_t smem_u32(const void* p) {
    return (uint32_t)__cvta_generic_to_shared(p);
}
__device__ __forceinline__ void cp16(uint32_t dst, const void* src, bool v) {
    asm volatile("cp.async.cg.shared.global [%0], [%1], 16, %2;\n"
                 :: "r"(dst), "l"(src), "r"(v ? 16 : 0));
}
#define CP_COMMIT() asm volatile("cp.async.commit_group;\n" ::: "memory")
#define CP_WAIT(n)  asm volatile("cp.async.wait_group %0;\n" :: "n"(n) : "memory")

__device__ __forceinline__ void ldsm_x4(uint32_t& r0, uint32_t& r1, uint32_t& r2, uint32_t& r3, uint32_t addr) {
    asm volatile("ldmatrix.sync.aligned.m8n8.x4.shared.b16 {%0,%1,%2,%3}, [%4];\n"
                 : "=r"(r0), "=r"(r1), "=r"(r2), "=r"(r3) : "r"(addr));
}
__device__ __forceinline__ void ldsm_x2(uint32_t& r0, uint32_t& r1, uint32_t addr) {
    asm volatile("ldmatrix.sync.aligned.m8n8.x2.shared.b16 {%0,%1}, [%2];\n"
                 : "=r"(r0), "=r"(r1) : "r"(addr));
}
__device__ __forceinline__ void mma_bf16(float* c, const uint32_t* a, const uint32_t* b) {
    asm volatile("mma.sync.aligned.m16n8k16.row.col.f32.bf16.bf16.f32 "
                 "{%0,%1,%2,%3}, {%4,%5,%6,%7}, {%8,%9}, {%0,%1,%2,%3};\n"
                 : "+f"(c[0]), "+f"(c[1]), "+f"(c[2]), "+f"(c[3])
                 : "r"(a[0]), "r"(a[1]), "r"(a[2]), "r"(a[3]), "r"(b[0]), "r"(b[1]));
}

// OP: 0 = plain, 1 = softplus(acc + bias[n])
template<int OP>
__global__ __launch_bounds__(256, 2) void mma_gemm(
    const bf16* __restrict__ Ah, const bf16* __restrict__ Al, int lda,
    const bf16* __restrict__ Wh, const bf16* __restrict__ Wl, int ldw,
    float* __restrict__ C, int ldc, int N, int kLen,
    const float* __restrict__ bias, int partStride)
{
    extern __shared__ __align__(16) bf16 sm[];
    uint32_t sbase = smem_u32(sm);

    int tid = threadIdx.x, lane = tid & 31, warp = tid >> 5;
    int wm = warp & 3, wn = warp >> 2;
    int m0 = blockIdx.y * BM, n0 = blockIdx.x * BN;
    int k0 = blockIdx.z * kLen;
    C += (size_t)blockIdx.z * partStride;

    // ---- global load mapping (per thread: 2 A-hi, 2 A-lo, 1 B-hi, 1 B-lo) ----
    int arow = tid >> 2, achunk = (tid & 3) * 8;
    int brow = tid >> 2;
    bool bval = (n0 + brow) < N;
    int browc = bval ? (n0 + brow) : 0;

    const bf16* pAh1 = Ah + (size_t)(m0 + arow) * lda + k0 + achunk;
    const bf16* pAh2 = Ah + (size_t)(m0 + 64 + arow) * lda + k0 + achunk;
    const bf16* pAl1 = Al + (size_t)(m0 + arow) * lda + k0 + achunk;
    const bf16* pAl2 = Al + (size_t)(m0 + 64 + arow) * lda + k0 + achunk;
    const bf16* pBh  = Wh + (size_t)browc * ldw + k0 + achunk;
    const bf16* pBl  = Wl + (size_t)browc * ldw + k0 + achunk;

    uint32_t oA1 = (S_AH + arow * RS + achunk) * 2;
    uint32_t oA2 = (S_AH + (64 + arow) * RS + achunk) * 2;
    uint32_t oL1 = oA1 + S_AL * 2 - S_AH * 2;
    uint32_t oL2 = oA2 + S_AL * 2 - S_AH * 2;
    uint32_t oBh = (S_BH + brow * RS + achunk) * 2;
    uint32_t oBl = (S_BL + brow * RS + achunk) * 2;

    // ---- ldmatrix lane offsets ----
    uint32_t aoff[2], boff[4];
    #pragma unroll
    for (int mi = 0; mi < 2; mi++) {
        int r = wm * 32 + mi * 16 + (lane & 15);
        int c = (lane >> 4) * 8;
        aoff[mi] = (uint32_t)((r * RS + c) * 2);
    }
    #pragma unroll
    for (int ni = 0; ni < 4; ni++) {
        int r = wn * 32 + ni * 8 + (lane & 7);
        int c = ((lane >> 3) & 1) * 8;
        boff[ni] = (uint32_t)((r * RS + c) * 2);
    }

    float acc[2][4][4];
    #pragma unroll
    for (int mi = 0; mi < 2; mi++)
        #pragma unroll
        for (int ni = 0; ni < 4; ni++)
            #pragma unroll
            for (int j = 0; j < 4; j++) acc[mi][ni][j] = 0.f;

    int KT = kLen / 32;

    // prologue: issue up to STAGES-1 stages; always commit STAGES-1 groups
    #pragma unroll
    for (int s = 0; s < STAGES - 1; s++) {
        if (s < KT) {
            uint32_t sb = sbase + s * STAGE_B;
            int kk = s * 32;
            cp16(sb + oA1, pAh1 + kk, true);
            cp16(sb + oA2, pAh2 + kk, true);
            cp16(sb + oL1, pAl1 + kk, true);
            cp16(sb + oL2, pAl2 + kk, true);
            cp16(sb + oBh, pBh + kk, bval);
            cp16(sb + oBl, pBl + kk, bval);
        }
        CP_COMMIT();
    }

    for (int kt = 0; kt < KT; kt++) {
        CP_WAIT(STAGES - 2);
        __syncthreads();

        int nk = kt + STAGES - 1;
        if (nk < KT) {
            uint32_t sb = sbase + (nk % STAGES) * STAGE_B;
            int kk = nk * 32;
            cp16(sb + oA1, pAh1 + kk, true);
            cp16(sb + oA2, pAh2 + kk, true);
            cp16(sb + oL1, pAl1 + kk, true);
            cp16(sb + oL2, pAl2 + kk, true);
            cp16(sb + oBh, pBh + kk, bval);
            cp16(sb + oBl, pBl + kk, bval);
        }
        CP_COMMIT();

        uint32_t base = sbase + (kt % STAGES) * STAGE_B;
        #pragma unroll
        for (int ks = 0; ks < 2; ks++) {
            uint32_t kb = base + ks * 32;   // +16 halves
            uint32_t ah[2][4], al[2][4], bh[4][2], bl[4][2];
            #pragma unroll
            for (int mi = 0; mi < 2; mi++) {
                ldsm_x4(ah[mi][0], ah[mi][1], ah[mi][2], ah[mi][3], kb + aoff[mi]);
                ldsm_x4(al[mi][0], al[mi][1], al[mi][2], al[mi][3], kb + S_AL * 2 + aoff[mi]);
            }
            #pragma unroll
            for (int ni = 0; ni < 4; ni++) {
                ldsm_x2(bh[ni][0], bh[ni][1], kb + S_BH * 2 + boff[ni]);
                ldsm_x2(bl[ni][0], bl[ni][1], kb + S_BL * 2 + boff[ni]);
            }
            #pragma unroll
            for (int mi = 0; mi < 2; mi++) {
                #pragma unroll
                for (int ni = 0; ni < 4; ni++) {
                    mma_bf16(acc[mi][ni], ah[mi], bh[ni]);
                    mma_bf16(acc[mi][ni], ah[mi], bl[ni]);
                    mma_bf16(acc[mi][ni], al[mi], bh[ni]);
                }
            }
        }
    }

    // ---- epilogue ----
    int crow0 = m0 + wm * 32, ccol0 = n0 + wn * 32;
    #pragma unroll
    for (int mi = 0; mi < 2; mi++) {
        #pragma unroll
        for (int ni = 0; ni < 4; ni++) {
            int r = crow0 + mi * 16 + (lane >> 2);
            int c = ccol0 + ni * 8 + (lane & 3) * 2;
            if (c < N) {
                float v0 = acc[mi][ni][0], v1 = acc[mi][ni][1];
                float v2 = acc[mi][ni][2], v3 = acc[mi][ni][3];
                if (OP == 1) {
                    float b0 = bias[c], b1 = bias[c + 1];
                    v0 += b0; v1 += b1; v2 += b0; v3 += b1;
                    v0 = (v0 > 20.f) ? v0 : log1pf(expf(v0));
                    v1 = (v1 > 20.f) ? v1 : log1pf(expf(v1));
                    v2 = (v2 > 20.f) ? v2 : log1pf(expf(v2));
                    v3 = (v3 > 20.f) ? v3 : log1pf(expf(v3));
                }
                *(float2*)(C + (size_t)r * ldc + c)       = make_float2(v0, v1);
                *(float2*)(C + (size_t)(r + 8) * ldc + c) = make_float2(v2, v3);
            }
        }
    }
}

// ---------------- split-K reduce for x_proj; emits dbl fp32 + dt bf16 hi/lo ----------------
__global__ void xreduce_kernel(const float* __restrict__ part,
                               float* __restrict__ dbl,
                               bf16* __restrict__ dthi, bf16* __restrict__ dtlo)
{
    int i = blockIdx.x * blockDim.x + threadIdx.x;
    if (i >= NTOK * DBL_W) return;
    float s = part[i] + part[i + NTOK*DBL_W] + part[i + 2*NTOK*DBL_W] + part[i + 3*NTOK*DBL_W];
    dbl[i] = s;
    int row = i / DBL_W, col = i - row * DBL_W;
    if (col < DT_RANK) {
        bf16 h, l; split1(s, h, l);
        dthi[row * DT_RANK + col] = h;
        dtlo[row * DT_RANK + col] = l;
    }
}

// ---------------- depthwise causal conv (D_CONV=4) + SiLU; emits fp32 + bf16 hi/lo ----------------
__global__ void conv_silu_kernel(const float* __restrict__ xz,
                                 const float* __restrict__ cw,
                                 const float* __restrict__ cb,
                                 float* __restrict__ xc,
                                 bf16* __restrict__ xch, bf16* __restrict__ xcl)
{
    int idx = blockIdx.x * blockDim.x + threadIdx.x;    // over NTOK * D_INNER/4
    if (idx >= NTOK * (D_INNER / 4)) return;
    int t = idx / (D_INNER / 4);
    int d = (idx - t * (D_INNER / 4)) * 4;
    int b = t / SEQ, l = t - b * SEQ;

    float a0 = cb[d], a1 = cb[d+1], a2 = cb[d+2], a3 = cb[d+3];
    float4 w0 = *(const float4*)(cw + (d+0)*D_CONV);
    float4 w1 = *(const float4*)(cw + (d+1)*D_CONV);
    float4 w2 = *(const float4*)(cw + (d+2)*D_CONV);
    float4 w3 = *(const float4*)(cw + (d+3)*D_CONV);
    const float* wp0 = &w0.x; const float* wp1 = &w1.x;
    const float* wp2 = &w2.x; const float* wp3 = &w3.x;

    #pragma unroll
    for (int k = 0; k < D_CONV; k++) {
        int ls = l - (D_CONV - 1) + k;
        if (ls >= 0) {
            float4 x = *(const float4*)(xz + ((size_t)(b * SEQ + ls) * (2 * D_INNER)) + d);
            a0 += x.x * wp0[k]; a1 += x.y * wp1[k];
            a2 += x.z * wp2[k]; a3 += x.w * wp3[k];
        }
    }
    a0 = a0 / (1.f + __expf(-a0));
    a1 = a1 / (1.f + __expf(-a1));
    a2 = a2 / (1.f + __expf(-a2));
    a3 = a3 / (1.f + __expf(-a3));

    size_t p = (size_t)t * D_INNER + d;
    *(float4*)(xc + p) = make_float4(a0, a1, a2, a3);
    bf16 h0,h1,h2,h3,l0,l1,l2,l3;
    split1(a0,h0,l0); split1(a1,h1,l1); split1(a2,h2,l2); split1(a3,h3,l3);
    *(bf162*)(xch + p)     = bf162(h0,h1);
    *(bf162*)(xch + p + 2) = bf162(h2,h3);
    *(bf162*)(xcl + p)     = bf162(l0,l1);
    *(bf162*)(xcl + p + 2) = bf162(l2,l3);
}

// ---------------- selective scan: 16 lanes per (b,d) channel; emits y bf16 hi/lo ----------------
__global__ void scan_kernel(const float* __restrict__ dt_arr,
                            const float* __restrict__ dbl,
                            const float* __restrict__ xc,
                            const float* __restrict__ xz,
                            const float* __restrict__ Alog,
                            const float* __restrict__ Dp,
                            bf16* __restrict__ yh, bf16* __restrict__ yl)
{
    int gid = blockIdx.x * blockDim.x + threadIdx.x;
    int ch = gid >> 4;
    int lane = gid & 15;
    if (ch >= BATCH * D_INNER) return;
    int b = ch / D_INNER, d = ch - b * D_INNER;

    float A = -__expf(Alog[d * D_STATE + lane]);
    float Dv = Dp[d];

    const float* dtp = dt_arr + (size_t)(b * SEQ) * D_INNER + d;
    const float* xp  = xc     + (size_t)(b * SEQ) * D_INNER + d;
    const float* zp  = xz     + (size_t)(b * SEQ) * (2 * D_INNER) + D_INNER + d;
    const float* bcp = dbl    + (size_t)(b * SEQ) * DBL_W;
    size_t ybase = (size_t)(b * SEQ) * D_INNER + d;

    float h = 0.f;
    for (int l = 0; l < SEQ; l++) {
        float dt = dtp[(size_t)l * D_INNER];
        float x  = xp [(size_t)l * D_INNER];
        float Bs = bcp[(size_t)l * DBL_W + DT_RANK + lane];
        float Cs = bcp[(size_t)l * DBL_W + DT_RANK + D_STATE + lane];

        h = h * __expf(dt * A) + (dt * x) * Bs;

        float p = h * Cs;
        p += __shfl_xor_sync(0xffffffffu, p, 8);
        p += __shfl_xor_sync(0xffffffffu, p, 4);
        p += __shfl_xor_sync(0xffffffffu, p, 2);
        p += __shfl_xor_sync(0xffffffffu, p, 1);

        if (lane == 0) {
            float z = zp[(size_t)l * (2 * D_INNER)];
            float y = (p + x * Dv) * (z / (1.f + __expf(-z)));
            bf16 hh, ll; split1(y, hh, ll);
            yh[ybase + (size_t)l * D_INNER] = hh;
            yl[ybase + (size_t)l * D_INNER] = ll;
        }
    }
}

// ---------------- launch ----------------
extern "C" void kernel_launch(void* const* d_in, const int* in_sizes, int n_in,
                              void* d_out, int out_size)
{
    const float* hidden     = (const float*)d_in[0];
    const float* in_proj_w  = (const float*)d_in[1];
    const float* conv_w     = (const float*)d_in[2];
    const float* conv_b     = (const float*)d_in[3];
    const float* x_proj_w   = (const float*)d_in[4];
    const float* dt_proj_w  = (const float*)d_in[5];
    const float* dt_proj_b  = (const float*)d_in[6];
    const float* A_log      = (const float*)d_in[7];
    const float* Dp         = (const float*)d_in[8];
    const float* out_proj_w = (const float*)d_in[9];
    const float* norm_w     = (const float*)d_in[10];
    const float* norm_b     = (const float*)d_in[11];
    const float* normf_w    = (const float*)d_in[12];
    const float* normf_b    = (const float*)d_in[13];
    float* out = (float*)d_out;

    float *p_resid, *p_hs, *p_xz, *p_xc, *p_dbl, *p_dt, *p_xpart;
    bf16 *p_normh, *p_norml, *p_xch, *p_xcl, *p_dtAh, *p_dtAl, *p_yh, *p_yl;
    bf16 *p_wih, *p_wil, *p_wxh, *p_wxl, *p_wdh, *p_wdl, *p_woh, *p_wol;
    cudaGetSymbolAddress((void**)&p_resid, g_resid);
    cudaGetSymbolAddress((void**)&p_hs,    g_hs);
    cudaGetSymbolAddress((void**)&p_xz,    g_xz);
    cudaGetSymbolAddress((void**)&p_xc,    g_xc);
    cudaGetSymbolAddress((void**)&p_dbl,   g_dbl);
    cudaGetSymbolAddress((void**)&p_dt,    g_dt);
    cudaGetSymbolAddress((void**)&p_xpart, g_xpart);
    cudaGetSymbolAddress((void**)&p_normh, g_normh);
    cudaGetSymbolAddress((void**)&p_norml, g_norml);
    cudaGetSymbolAddress((void**)&p_xch,   g_xch);
    cudaGetSymbolAddress((void**)&p_xcl,   g_xcl);
    cudaGetSymbolAddress((void**)&p_dtAh,  g_dtAh);
    cudaGetSymbolAddress((void**)&p_dtAl,  g_dtAl);
    cudaGetSymbolAddress((void**)&p_yh,    g_yh);
    cudaGetSymbolAddress((void**)&p_yl,    g_yl);
    cudaGetSymbolAddress((void**)&p_wih,   g_wih);
    cudaGetSymbolAddress((void**)&p_wil,   g_wil);
    cudaGetSymbolAddress((void**)&p_wxh,   g_wxh);
    cudaGetSymbolAddress((void**)&p_wxl,   g_wxl);
    cudaGetSymbolAddress((void**)&p_wdh,   g_wdh);
    cudaGetSymbolAddress((void**)&p_wdl,   g_wdl);
    cudaGetSymbolAddress((void**)&p_woh,   g_woh);
    cudaGetSymbolAddress((void**)&p_wol,   g_wol);

    cudaFuncSetAttribute(mma_gemm<0>, cudaFuncAttributeMaxDynamicSharedMemorySize, GEMM_SMEM);
    cudaFuncSetAttribute(mma_gemm<1>, cudaFuncAttributeMaxDynamicSharedMemorySize, GEMM_SMEM);

    // ---- weight conversion (once per launch) ----
    {
        int n;
        n = N_LAYER*2*D_INNER*D_MODEL/4;
        split4_kernel<<<(n+255)/256, 256>>>((const float4*)in_proj_w,  (bf162*)p_wih, (bf162*)p_wil, n);
        n = N_LAYER*DBL_W*D_INNER/4;
        split4_kernel<<<(n+255)/256, 256>>>((const float4*)x_proj_w,   (bf162*)p_wxh, (bf162*)p_wxl, n);
        n = N_LAYER*D_INNER*DT_RANK/4;
        split4_kernel<<<(n+255)/256, 256>>>((const float4*)dt_proj_w,  (bf162*)p_wdh, (bf162*)p_wdl, n);
        n = N_LAYER*D_MODEL*D_INNER/4;
        split4_kernel<<<(n+255)/256, 256>>>((const float4*)out_proj_w, (bf162*)p_woh, (bf162*)p_wol, n);
    }

    for (int layer = 0; layer < N_LAYER; layer++) {
        const float* src = (layer == 0) ? hidden : p_hs;

        addln_kernel<<<NTOK, 256>>>(src,
                                    norm_w + layer * D_MODEL, norm_b + layer * D_MODEL,
                                    p_resid, nullptr, p_normh, p_norml, layer == 0 ? 1 : 0);

        // in_proj: [2048,1024] x [4096,1024]^T -> [2048,4096]
        mma_gemm<0><<<dim3(2*D_INNER/BN, NTOK/BM, 1), 256, GEMM_SMEM>>>(
            p_normh, p_norml, D_MODEL,
            p_wih + (size_t)layer*2*D_INNER*D_MODEL, p_wil + (size_t)layer*2*D_INNER*D_MODEL, D_MODEL,
            p_xz, 2*D_INNER, 2*D_INNER, D_MODEL, nullptr, 0);

        conv_silu_kernel<<<(NTOK*(D_INNER/4) + 255)/256, 256>>>(
            p_xz, conv_w + (size_t)layer*D_INNER*D_CONV,
            conv_b + (size_t)layer*D_INNER, p_xc, p_xch, p_xcl);

        // x_proj split-K: [2048,2048] x [96,2048]^T -> 4 partials of [2048,96]
        mma_gemm<0><<<dim3((DBL_W + BN - 1)/BN, NTOK/BM, KSPLIT), 256, GEMM_SMEM>>>(
            p_xch, p_xcl, D_INNER,
            p_wxh + (size_t)layer*DBL_W*D_INNER, p_wxl + (size_t)layer*DBL_W*D_INNER, D_INNER,
            p_xpart, DBL_W, DBL_W, D_INNER/KSPLIT, nullptr, NTOK*DBL_W);

        xreduce_kernel<<<(NTOK*DBL_W + 255)/256, 256>>>(p_xpart, p_dbl, p_dtAh, p_dtAl);

        // dt_proj + softplus: [2048,64] x [2048,64]^T -> [2048,2048]
        mma_gemm<1><<<dim3(D_INNER/BN, NTOK/BM, 1), 256, GEMM_SMEM>>>(
            p_dtAh, p_dtAl, DT_RANK,
            p_wdh + (size_t)layer*D_INNER*DT_RANK, p_wdl + (size_t)layer*D_INNER*DT_RANK, DT_RANK,
            p_dt, D_INNER, D_INNER, DT_RANK,
            dt_proj_b + (size_t)layer*D_INNER, 0);

        scan_kernel<<<(BATCH*D_INNER*16)/256, 256>>>(
            p_dt, p_dbl, p_xc, p_xz,
            A_log + (size_t)layer*D_INNER*D_STATE,
            Dp + (size_t)layer*D_INNER, p_yh, p_yl);

        // out_proj: [2048,2048] x [1024,2048]^T -> [2048,1024]
        mma_gemm<0><<<dim3(D_MODEL/BN, NTOK/BM, 1), 256, GEMM_SMEM>>>(
            p_yh, p_yl, D_INNER,
            p_woh + (size_t)layer*D_MODEL*D_INNER, p_wol + (size_t)layer*D_MODEL*D_INNER, D_INNER,
            p_hs, D_MODEL, D_MODEL, D_INNER, nullptr, 0);
    }

    addln_kernel<<<NTOK, 256>>>(p_hs, normf_w, normf_b, p_resid, out, nullptr, nullptr, 0);
}